// round 6
// baseline (speedup 1.0000x reference)
#include <cuda_runtime.h>
#include <math.h>
#include <stdint.h>

// S=64, W=128, D=256, HW=256, HS=512, C=13

// ---------------------------------------------------------------------------
// Scratch (static device globals — no allocation allowed)
// ---------------------------------------------------------------------------
__device__ __align__(16) float g_Gi[2u*128*64*768];   // [d][w][s][768]
__device__ __align__(16) float g_H[2u*129*64*256];    // [d][w][s][256]
__device__ __align__(16) float g_Uw[64u*128*512];     // [s][w][512]
__device__ __align__(16) float g_sent[64*512];
__device__ __align__(16) float g_sgi[2*64*1536];
__device__ __align__(16) float g_sentenc[64*1024];
__device__ __align__(16) float g_usent[64*1024];

__device__ __forceinline__ float sigf(float x) { return 1.f / (1.f + expf(-x)); }

__device__ __forceinline__ uint32_t f2tf(float f) {
    uint32_t u;
    asm("cvt.rna.tf32.f32 %0, %1;" : "=r"(u) : "f"(f));
    return u;
}

__device__ __forceinline__ void mma8(float c[4], const uint32_t a[4], const uint32_t b[2]) {
    asm volatile(
        "mma.sync.aligned.m16n8k8.row.col.f32.tf32.tf32.f32 "
        "{%0,%1,%2,%3}, {%4,%5,%6,%7}, {%8,%9}, {%0,%1,%2,%3};"
        : "+f"(c[0]), "+f"(c[1]), "+f"(c[2]), "+f"(c[3])
        : "r"(a[0]), "r"(a[1]), "r"(a[2]), "r"(a[3]), "r"(b[0]), "r"(b[1]));
}

__device__ __forceinline__ uint32_t smem_u32(const void* p) {
    uint32_t a;
    asm("{ .reg .u64 t; cvta.to.shared.u64 t, %1; cvt.u32.u64 %0, t; }"
        : "=r"(a) : "l"(p));
    return a;
}

__device__ __forceinline__ void st_dsmem_f32(uint32_t local_addr, int rank, float v) {
    uint32_t ra;
    asm volatile("mapa.shared::cluster.u32 %0, %1, %2;" : "=r"(ra) : "r"(local_addr), "r"(rank));
    asm volatile("st.shared::cluster.f32 [%0], %1;" :: "r"(ra), "f"(v) : "memory");
}

// ---------------------------------------------------------------------------
// K0: fill attention-weight outputs (exact ones)
// ---------------------------------------------------------------------------
__global__ void k0_init(float* __restrict__ out, int ones_n) {
    int i = blockIdx.x * blockDim.x + threadIdx.x;
    int stride = gridDim.x * blockDim.x;
    for (int j = i; j < ones_n; j += stride) out[j] = 1.0f;
}

// ---------------------------------------------------------------------------
// Unified tf32 tensor-core GEMM: C[M,N] = act(A[M,K] @ B[N,K]^T + bias)
// (unchanged from R5)
// ---------------------------------------------------------------------------
template<int MODE>
__global__ void __launch_bounds__(256) gemm_tf32(const int* __restrict__ doc,
                                                 const float* __restrict__ Aext,
                                                 const float* __restrict__ Bw,
                                                 const float* __restrict__ bias) {
    constexpr int K    = (MODE == 0) ? 256 : (MODE == 3) ? 1024 : 512;
    constexpr bool TANH = (MODE == 1) || (MODE == 3);
    constexpr int MV   = (MODE >= 2) ? 64 : 128;   // valid rows

    __shared__ float As[128][36];
    __shared__ float Bs[64][36];
    __shared__ int toks[128];

    const int tid = threadIdx.x;
    const int z   = blockIdx.z;
    const int j0  = blockIdx.x * 64;
    const int r0  = blockIdx.y * 128;

    const float* B = Bw;
    const float* bi = bias;
    float* out;
    int ldC;
    if constexpr (MODE == 0) {
        B  += (size_t)z * 768 * 256;
        bi += z * 768;
        out = g_Gi + (size_t)z * 8192 * 768;
        ldC = 768;
    } else if constexpr (MODE == 1) {
        out = g_Uw; ldC = 512;
    } else if constexpr (MODE == 2) {
        B  += (size_t)z * 1536 * 512;
        bi += z * 1536;
        out = g_sgi + (size_t)z * 64 * 1536;
        ldC = 1536;
    } else {
        out = g_usent; ldC = 1024;
    }

    if constexpr (MODE == 0) {
        if (tid < 128) {
            int s = tid & 63, wl = tid >> 6;
            toks[tid] = doc[s * 128 + (r0 >> 6) + wl];
        }
        __syncthreads();
    }

    const int lane = tid & 31, wid = tid >> 5;
    const int g = lane >> 2, t = lane & 3;
    const int mbase = (wid & 1) * 64;
    const int nbase = (wid >> 1) * 16;

    float acc[4][2][4] = {};

    for (int kt = 0; kt < K; kt += 32) {
#pragma unroll
        for (int it = 0; it < 4; ++it) {
            int f = tid + it * 256;
            int row = f >> 3;
            int c4 = (f & 7) << 2;
            int kg = kt + c4;
            const float* src;
            if constexpr (MODE == 0) {
                src = Aext + (size_t)toks[row] * 256 + kg;
            } else if constexpr (MODE == 1) {
                int r = r0 + row;
                int s = r >> 7, w = r & 127;
                int dsel = kg >> 8, kl = kg & 255;
                src = g_H + (((size_t)dsel * 129 + (w + 1)) * 64 + s) * 256 + kl;
            } else if constexpr (MODE == 2) {
                int rr = row < 64 ? row : 63;
                src = g_sent + (size_t)rr * 512 + kg;
            } else {
                int rr = row < 64 ? row : 63;
                src = g_sentenc + (size_t)rr * 1024 + kg;
            }
            float4 v = *(const float4*)src;
            As[row][c4 + 0] = __uint_as_float(f2tf(v.x));
            As[row][c4 + 1] = __uint_as_float(f2tf(v.y));
            As[row][c4 + 2] = __uint_as_float(f2tf(v.z));
            As[row][c4 + 3] = __uint_as_float(f2tf(v.w));
        }
#pragma unroll
        for (int it = 0; it < 2; ++it) {
            int f = tid + it * 256;
            int row = f >> 3;
            int c4 = (f & 7) << 2;
            float4 v = *(const float4*)(B + (size_t)(j0 + row) * K + kt + c4);
            Bs[row][c4 + 0] = __uint_as_float(f2tf(v.x));
            Bs[row][c4 + 1] = __uint_as_float(f2tf(v.y));
            Bs[row][c4 + 2] = __uint_as_float(f2tf(v.z));
            Bs[row][c4 + 3] = __uint_as_float(f2tf(v.w));
        }
        __syncthreads();

#pragma unroll
        for (int kc = 0; kc < 32; kc += 8) {
            uint32_t a[4][4], b[2][2];
#pragma unroll
            for (int mt = 0; mt < 4; ++mt) {
                int rr = mbase + mt * 16 + g;
                a[mt][0] = __float_as_uint(As[rr][kc + t]);
                a[mt][1] = __float_as_uint(As[rr + 8][kc + t]);
                a[mt][2] = __float_as_uint(As[rr][kc + t + 4]);
                a[mt][3] = __float_as_uint(As[rr + 8][kc + t + 4]);
            }
#pragma unroll
            for (int nt = 0; nt < 2; ++nt) {
                int nn = nbase + nt * 8 + g;
                b[nt][0] = __float_as_uint(Bs[nn][kc + t]);
                b[nt][1] = __float_as_uint(Bs[nn][kc + t + 4]);
            }
#pragma unroll
            for (int mt = 0; mt < 4; ++mt)
#pragma unroll
                for (int nt = 0; nt < 2; ++nt)
                    mma8(acc[mt][nt], a[mt], b[nt]);
        }
        __syncthreads();
    }

#pragma unroll
    for (int mt = 0; mt < 4; ++mt) {
#pragma unroll
        for (int nt = 0; nt < 2; ++nt) {
            int col = j0 + nbase + nt * 8 + 2 * t;
            float b0 = bi[col], b1 = bi[col + 1];
            int row = mbase + mt * 16 + g;
#pragma unroll
            for (int half = 0; half < 2; ++half) {
                int r = row + half * 8;
                if (r < MV) {
                    float v0 = acc[mt][nt][half * 2 + 0] + b0;
                    float v1 = acc[mt][nt][half * 2 + 1] + b1;
                    if (TANH) { v0 = tanhf(v0); v1 = tanhf(v1); }
                    float2 st = make_float2(v0, v1);
                    *(float2*)(out + (size_t)(r0 + r) * ldC + col) = st;
                }
            }
        }
    }
}

// ---------------------------------------------------------------------------
// K2: word GRU recurrence — tensor-core + 8-CTA CLUSTER with DSMEM h-exchange.
// Cluster = the 8 ktile-CTAs of one (dir, sgroup); rank = ktile (32 h-cols).
// Per step: mma gh[96,8] from own SMEM hbuf (double-buffered), GRU cell,
// scatter own 32 h-cols into all 8 peers' next-parity hbuf via st.shared::cluster,
// one barrier.cluster per step. No L2 in the recurrence loop.
// ---------------------------------------------------------------------------
__global__ void __launch_bounds__(384, 1) __cluster_dims__(8, 1, 1)
k2_rec(const float* __restrict__ Wh, const float* __restrict__ bh_g) {
    const int rank = blockIdx.x & 7;         // ktile
    const int gid  = blockIdx.x >> 3;        // (d, sg) group
    const int d  = gid >> 3;
    const int sg = gid & 7;
    const int k0 = rank * 32;
    const int s0 = sg * 8;
    const int tid  = threadIdx.x;
    const int lane = tid & 31;
    const int wu   = tid >> 5;       // 0..11
    const int mu   = wu % 6;         // m-tile (rows mu*16 .. +15 of 96)
    const int kh   = wu / 6;         // k-half (0:[0,128) 1:[128,256))
    const int g    = lane >> 2;      // 0..7
    const int t    = lane & 3;       // 0..3

    extern __shared__ float sm[];
    float* ws   = sm;                 // [96][260] weight staging (init only)
    float* hb0  = sm + 96 * 260;      // [8][264] h parity 0
    float* hb1  = hb0 + 8 * 264;      // [8][264] h parity 1
    float* gh   = hb1 + 8 * 264;      // [2][8][100] per-k-half partials

    // ---- init: stage weight slice, preload A fragments into registers ----
    const float* WhD = Wh + (size_t)d * 768 * 256;
    for (int e = tid; e < 96 * 256; e += 384) {
        int rr = e >> 8, c = e & 255;
        int third = rr / 32, kr = rr % 32;
        ws[rr * 260 + c] = WhD[(size_t)(third * 256 + k0 + kr) * 256 + c];
    }
    // zero h(0) buffer (own SMEM; every CTA zeroes its own)
    for (int i = tid; i < 8 * 264; i += 384) hb0[i] = 0.f;
    __syncthreads();

    uint32_t afr[16][4];
    {
        const int row0 = mu * 16 + g;
#pragma unroll
        for (int ks = 0; ks < 16; ++ks) {
            int kc = kh * 128 + ks * 8;
            afr[ks][0] = f2tf(ws[row0 * 260 + kc + t]);
            afr[ks][1] = f2tf(ws[(row0 + 8) * 260 + kc + t]);
            afr[ks][2] = f2tf(ws[row0 * 260 + kc + t + 4]);
            afr[ks][3] = f2tf(ws[(row0 + 8) * 260 + kc + t + 4]);
        }
    }

    // epilogue mapping + biases (tid < 256: sl = sentence, kk = h-col in tile)
    const int sl = tid >> 5;
    const int kk = tid & 31;
    float bhr = 0.f, bhz = 0.f, bhn = 0.f;
    if (tid < 256) {
        bhr = bh_g[d * 768 + k0 + kk];
        bhz = bh_g[d * 768 + 256 + k0 + kk];
        bhn = bh_g[d * 768 + 512 + k0 + kk];
    }
    const uint32_t hb_u32[2] = { smem_u32(hb0), smem_u32(hb1) };
    const uint32_t dst_off = (uint32_t)(sl * 264 + k0 + kk) * 4u;

    // prefetch gi(0)
    float gir = 0.f, giz = 0.f, gin = 0.f;
    if (tid < 256) {
        const float* gi = g_Gi + (((size_t)d * 128 + 0) * 64 + (s0 + sl)) * 768;
        gir = gi[k0 + kk];
        giz = gi[256 + k0 + kk];
        gin = gi[512 + k0 + kk];
    }

    // all CTAs ready (hb0 zeroed, weights staged) before any remote access
    asm volatile("barrier.cluster.arrive.aligned;" ::: "memory");
    asm volatile("barrier.cluster.wait.aligned;" ::: "memory");

    for (int w = 0; w < 128; ++w) {
        const float* cur = (w & 1) ? hb1 : hb0;

        // mma: c[16 rows x 8 sent] per warp, K over this warp's 128-half
        float c[4] = {0.f, 0.f, 0.f, 0.f};
#pragma unroll
        for (int ks = 0; ks < 16; ++ks) {
            int kc = kh * 128 + ks * 8;
            uint32_t bfr[2];
            bfr[0] = f2tf(cur[g * 264 + kc + t]);
            bfr[1] = f2tf(cur[g * 264 + kc + t + 4]);
            mma8(c, afr[ks], bfr);
        }
        {
            float* base = gh + kh * 800;
            int r0w = mu * 16 + g;
            base[(2 * t) * 100 + r0w]         = c[0];
            base[(2 * t + 1) * 100 + r0w]     = c[1];
            base[(2 * t) * 100 + r0w + 8]     = c[2];
            base[(2 * t + 1) * 100 + r0w + 8] = c[3];
        }
        __syncthreads();

        // GRU cell + DSMEM scatter: 256 threads, one (sentence, h-col) each
        if (tid < 256) {
            float sr = gh[sl * 100 + kk]       + gh[800 + sl * 100 + kk];
            float sz = gh[sl * 100 + 32 + kk]  + gh[800 + sl * 100 + 32 + kk];
            float sn = gh[sl * 100 + 64 + kk]  + gh[800 + sl * 100 + 64 + kk];
            float r = sigf(gir + sr + bhr);
            float z = sigf(giz + sz + bhz);
            float n = tanhf(gin + r * (sn + bhn));
            float hprev = cur[sl * 264 + k0 + kk];
            float hnew = (1.f - z) * n + z * hprev;

            // scatter to all 8 cluster CTAs' next-parity hbuf
            uint32_t dst_local = hb_u32[(w + 1) & 1] + dst_off;
#pragma unroll
            for (int rr = 0; rr < 8; ++rr) st_dsmem_f32(dst_local, rr, hnew);

            // fire-and-forget global store for k3 (read after kernel end)
            g_H[(((size_t)d * 129 + (w + 1)) * 64 + (s0 + sl)) * 256 + k0 + kk] = hnew;

            // prefetch gi(w+1) — hidden under the cluster barrier
            if (w < 127) {
                const float* gi = g_Gi + (((size_t)d * 128 + (w + 1)) * 64 + (s0 + sl)) * 768;
                gir = gi[k0 + kk];
                giz = gi[256 + k0 + kk];
                gin = gi[512 + k0 + kk];
            }
        }

        // one cluster barrier per step: publishes remote h, reuses gh safely
        asm volatile("barrier.cluster.arrive.aligned;" ::: "memory");
        asm volatile("barrier.cluster.wait.aligned;" ::: "memory");
    }
}

// K4: sent_summ[s][j] = sum_w u_word[s][w][j]
__global__ void k4_reduce() {
    int s = blockIdx.x;
    int j = blockIdx.y * 128 + threadIdx.x;
    const float* p = g_Uw + (size_t)s * 128 * 512 + j;
    float a = 0.f;
    for (int w = 0; w < 128; ++w) a += p[w * 512];
    g_sent[s * 512 + j] = a;
}

// K5b: sentence GRU gate with zero hidden state
__global__ void k5b_gate(const float* __restrict__ sbh) {
    int idx = blockIdx.x * 256 + threadIdx.x;
    if (idx >= 2 * 64 * 512) return;
    int d = idx >> 15;
    int rem = idx & 32767;
    int s = rem >> 9;
    int j = rem & 511;
    const float* gi = g_sgi + ((size_t)d * 64 + s) * 1536;
    float gir = gi[j], giz = gi[512 + j], gin = gi[1024 + j];
    float hr = sbh[d * 1536 + j];
    float hz = sbh[d * 1536 + 512 + j];
    float hn = sbh[d * 1536 + 1024 + j];
    float r = sigf(gir + hr);
    float z = sigf(giz + hz);
    float n = tanhf(gin + r * hn);
    g_sentenc[s * 1024 + d * 512 + j] = (1.f - z) * n;
}

// K6: doc sum, logits, log_softmax
__global__ void k6_final(const float* __restrict__ doW, const float* __restrict__ dob,
                         float* __restrict__ out, int out_size) {
    __shared__ float doc[1024];
    __shared__ float lg[16];
    int tid = threadIdx.x;
    for (int j = tid; j < 1024; j += 256) {
        float a = 0.f;
        for (int s = 0; s < 64; ++s) a += g_usent[s * 1024 + j];
        doc[j] = a;
    }
    __syncthreads();
    int wid = tid >> 5, lane = tid & 31;
    for (int c = wid; c < 13; c += 8) {
        float p = 0.f;
        for (int k = lane; k < 1024; k += 32) p += doc[k] * doW[c * 1024 + k];
#pragma unroll
        for (int o = 16; o > 0; o >>= 1) p += __shfl_xor_sync(0xffffffffu, p, o);
        if (lane == 0) lg[c] = p + dob[c];
    }
    __syncthreads();
    if (tid == 0) {
        float m = lg[0];
        for (int c = 1; c < 13; ++c) m = fmaxf(m, lg[c]);
        float sum = 0.f;
        for (int c = 0; c < 13; ++c) sum += expf(lg[c] - m);
        float lse = m + logf(sum);
        for (int c = 0; c < 13; ++c) out[out_size - 13 + c] = lg[c] - lse;
    }
}

// ---------------------------------------------------------------------------
extern "C" void kernel_launch(void* const* d_in, const int* in_sizes, int n_in,
                              void* d_out, int out_size) {
    const int*   doc = (const int*)  d_in[0];
    const float* emb = (const float*)d_in[1];
    const float* wWi = (const float*)d_in[2];
    const float* wWh = (const float*)d_in[3];
    const float* wbi = (const float*)d_in[4];
    const float* wbh = (const float*)d_in[5];
    const float* sWi = (const float*)d_in[6];
    const float* sbi = (const float*)d_in[8];
    const float* sbh = (const float*)d_in[9];
    const float* waW = (const float*)d_in[10];
    const float* wab = (const float*)d_in[11];
    const float* saW = (const float*)d_in[13];
    const float* sab = (const float*)d_in[14];
    const float* doW = (const float*)d_in[16];
    const float* dob = (const float*)d_in[17];
    float* out = (float*)d_out;

    // smem: ws 96*260 + 2 x hbuf 8*264 + gh 1600 floats
    const int SMEM_K2 = (96 * 260 + 2 * 8 * 264 + 1600) * 4;  // 123,136 B
    cudaFuncSetAttribute(k2_rec, cudaFuncAttributeMaxDynamicSharedMemorySize, SMEM_K2);

    k0_init<<<64, 256>>>(out, out_size - 13);
    gemm_tf32<0><<<dim3(12, 64, 2), 256>>>(doc, emb, wWi, wbi);
    k2_rec<<<128, 384, SMEM_K2>>>(wWh, wbh);
    gemm_tf32<1><<<dim3(8, 64, 1), 256>>>(nullptr, nullptr, waW, wab);
    k4_reduce<<<dim3(64, 4), 128>>>();
    gemm_tf32<2><<<dim3(24, 1, 2), 256>>>(nullptr, nullptr, sWi, sbi);
    k5b_gate<<<256, 256>>>(sbh);
    gemm_tf32<3><<<dim3(16, 1, 1), 256>>>(nullptr, nullptr, saW, sab);
    k6_final<<<1, 256>>>(doW, dob, out, out_size);
}

// round 8
// speedup vs baseline: 1.2963x; 1.2963x over previous
#include <cuda_runtime.h>
#include <math.h>
#include <stdint.h>

// S=64, W=128, D=256, HW=256, HS=512, C=13

// ---------------------------------------------------------------------------
// Scratch (static device globals — no allocation allowed)
// ---------------------------------------------------------------------------
__device__ __align__(16) float g_Gi[2u*128*64*768];   // [d][w][s][768]
__device__ __align__(16) float g_H[2u*129*64*256];    // [d][w][s][256] (k3 input)
__device__ __align__(16) float g_Uw[64u*128*512];     // [s][w][512]
__device__ __align__(16) float g_sent[64*512];
__device__ __align__(16) float g_sgi[2*64*1536];
__device__ __align__(16) float g_sentenc[64*1024];
__device__ __align__(16) float g_usent[64*1024];
// tagged h-exchange ring: [d][sg][slot(4)][sent(8)][col(256)] of {h_bits, tag}
__device__ __align__(16) uint2 g_Hx[2*8*4*8*256];

__device__ __forceinline__ float sigf(float x) { return 1.f / (1.f + expf(-x)); }

__device__ __forceinline__ uint32_t f2tf(float f) {
    uint32_t u;
    asm("cvt.rna.tf32.f32 %0, %1;" : "=r"(u) : "f"(f));
    return u;
}

__device__ __forceinline__ void mma8(float c[4], const uint32_t a[4], const uint32_t b[2]) {
    asm volatile(
        "mma.sync.aligned.m16n8k8.row.col.f32.tf32.tf32.f32 "
        "{%0,%1,%2,%3}, {%4,%5,%6,%7}, {%8,%9}, {%0,%1,%2,%3};"
        : "+f"(c[0]), "+f"(c[1]), "+f"(c[2]), "+f"(c[3])
        : "r"(a[0]), "r"(a[1]), "r"(a[2]), "r"(a[3]), "r"(b[0]), "r"(b[1]));
}

// ---------------------------------------------------------------------------
// K0: attention-weight ones + reset h-exchange ring tags (replay safety)
// ---------------------------------------------------------------------------
__global__ void k0_init(float* __restrict__ out, int ones_n) {
    int i = blockIdx.x * blockDim.x + threadIdx.x;
    int stride = gridDim.x * blockDim.x;
    for (int j = i; j < ones_n; j += stride) out[j] = 1.0f;
    // g_Hx: slot 0 = state h(0): value 0, tag 0; slots 1..3: tag invalid
    for (int j = i; j < 2 * 8 * 4 * 8 * 256; j += stride) {
        int slot = (j >> 11) & 3;
        g_Hx[j] = make_uint2(0u, slot == 0 ? 0u : 0xFFFFFFFFu);
    }
}

// ---------------------------------------------------------------------------
// Unified tf32 tensor-core GEMM (unchanged from R5)
// ---------------------------------------------------------------------------
template<int MODE>
__global__ void __launch_bounds__(256) gemm_tf32(const int* __restrict__ doc,
                                                 const float* __restrict__ Aext,
                                                 const float* __restrict__ Bw,
                                                 const float* __restrict__ bias) {
    constexpr int K    = (MODE == 0) ? 256 : (MODE == 3) ? 1024 : 512;
    constexpr bool TANH = (MODE == 1) || (MODE == 3);
    constexpr int MV   = (MODE >= 2) ? 64 : 128;   // valid rows

    __shared__ float As[128][36];
    __shared__ float Bs[64][36];
    __shared__ int toks[128];

    const int tid = threadIdx.x;
    const int z   = blockIdx.z;
    const int j0  = blockIdx.x * 64;
    const int r0  = blockIdx.y * 128;

    const float* B = Bw;
    const float* bi = bias;
    float* out;
    int ldC;
    if constexpr (MODE == 0) {
        B  += (size_t)z * 768 * 256;
        bi += z * 768;
        out = g_Gi + (size_t)z * 8192 * 768;
        ldC = 768;
    } else if constexpr (MODE == 1) {
        out = g_Uw; ldC = 512;
    } else if constexpr (MODE == 2) {
        B  += (size_t)z * 1536 * 512;
        bi += z * 1536;
        out = g_sgi + (size_t)z * 64 * 1536;
        ldC = 1536;
    } else {
        out = g_usent; ldC = 1024;
    }

    if constexpr (MODE == 0) {
        if (tid < 128) {
            int s = tid & 63, wl = tid >> 6;
            toks[tid] = doc[s * 128 + (r0 >> 6) + wl];
        }
        __syncthreads();
    }

    const int lane = tid & 31, wid = tid >> 5;
    const int g = lane >> 2, t = lane & 3;
    const int mbase = (wid & 1) * 64;
    const int nbase = (wid >> 1) * 16;

    float acc[4][2][4] = {};

    for (int kt = 0; kt < K; kt += 32) {
#pragma unroll
        for (int it = 0; it < 4; ++it) {
            int f = tid + it * 256;
            int row = f >> 3;
            int c4 = (f & 7) << 2;
            int kg = kt + c4;
            const float* src;
            if constexpr (MODE == 0) {
                src = Aext + (size_t)toks[row] * 256 + kg;
            } else if constexpr (MODE == 1) {
                int r = r0 + row;
                int s = r >> 7, w = r & 127;
                int dsel = kg >> 8, kl = kg & 255;
                src = g_H + (((size_t)dsel * 129 + (w + 1)) * 64 + s) * 256 + kl;
            } else if constexpr (MODE == 2) {
                int rr = row < 64 ? row : 63;
                src = g_sent + (size_t)rr * 512 + kg;
            } else {
                int rr = row < 64 ? row : 63;
                src = g_sentenc + (size_t)rr * 1024 + kg;
            }
            float4 v = *(const float4*)src;
            As[row][c4 + 0] = __uint_as_float(f2tf(v.x));
            As[row][c4 + 1] = __uint_as_float(f2tf(v.y));
            As[row][c4 + 2] = __uint_as_float(f2tf(v.z));
            As[row][c4 + 3] = __uint_as_float(f2tf(v.w));
        }
#pragma unroll
        for (int it = 0; it < 2; ++it) {
            int f = tid + it * 256;
            int row = f >> 3;
            int c4 = (f & 7) << 2;
            float4 v = *(const float4*)(B + (size_t)(j0 + row) * K + kt + c4);
            Bs[row][c4 + 0] = __uint_as_float(f2tf(v.x));
            Bs[row][c4 + 1] = __uint_as_float(f2tf(v.y));
            Bs[row][c4 + 2] = __uint_as_float(f2tf(v.z));
            Bs[row][c4 + 3] = __uint_as_float(f2tf(v.w));
        }
        __syncthreads();

#pragma unroll
        for (int kc = 0; kc < 32; kc += 8) {
            uint32_t a[4][4], b[2][2];
#pragma unroll
            for (int mt = 0; mt < 4; ++mt) {
                int rr = mbase + mt * 16 + g;
                a[mt][0] = __float_as_uint(As[rr][kc + t]);
                a[mt][1] = __float_as_uint(As[rr + 8][kc + t]);
                a[mt][2] = __float_as_uint(As[rr][kc + t + 4]);
                a[mt][3] = __float_as_uint(As[rr + 8][kc + t + 4]);
            }
#pragma unroll
            for (int nt = 0; nt < 2; ++nt) {
                int nn = nbase + nt * 8 + g;
                b[nt][0] = __float_as_uint(Bs[nn][kc + t]);
                b[nt][1] = __float_as_uint(Bs[nn][kc + t + 4]);
            }
#pragma unroll
            for (int mt = 0; mt < 4; ++mt)
#pragma unroll
                for (int nt = 0; nt < 2; ++nt)
                    mma8(acc[mt][nt], a[mt], b[nt]);
        }
        __syncthreads();
    }

#pragma unroll
    for (int mt = 0; mt < 4; ++mt) {
#pragma unroll
        for (int nt = 0; nt < 2; ++nt) {
            int col = j0 + nbase + nt * 8 + 2 * t;
            float b0 = bi[col], b1 = bi[col + 1];
            int row = mbase + mt * 16 + g;
#pragma unroll
            for (int half = 0; half < 2; ++half) {
                int r = row + half * 8;
                if (r < MV) {
                    float v0 = acc[mt][nt][half * 2 + 0] + b0;
                    float v1 = acc[mt][nt][half * 2 + 1] + b1;
                    if (TANH) { v0 = tanhf(v0); v1 = tanhf(v1); }
                    float2 st = make_float2(v0, v1);
                    *(float2*)(out + (size_t)(r0 + r) * ldC + col) = st;
                }
            }
        }
    }
}

// ---------------------------------------------------------------------------
// K2: word GRU recurrence — tensor cores + TAGGED-DATA L2 exchange.
// 128 blocks = dir(2) x ktile(8 x 32 h-cols) x sgroup(8 x 8 sentences).
// Exchange: each h word carries its step tag in an 8B {val,tag} pair
// (single stcg, atomic in L2). Consumers poll the data itself — detection
// IS data arrival: one L2 hop per step instead of flag+data two hops.
// 4-slot ring (skew bound = 1 step); tags reset in k0 for graph replays.
// ---------------------------------------------------------------------------
__global__ void __launch_bounds__(384, 1) k2_rec(const float* __restrict__ Wh,
                                                 const float* __restrict__ bh_g) {
    const int b  = blockIdx.x;
    const int d  = b >> 6;
    const int kt = (b >> 3) & 7;
    const int sg = b & 7;
    const int k0 = kt * 32;
    const int s0 = sg * 8;
    const int tid  = threadIdx.x;
    const int lane = tid & 31;
    const int wu   = tid >> 5;       // 0..11
    const int mu   = wu % 6;         // m-tile (rows mu*16 .. +15 of 96)
    const int kh   = wu / 6;         // k-half (0:[0,128) 1:[128,256))
    const int g    = lane >> 2;      // 0..7
    const int t    = lane & 3;       // 0..3

    extern __shared__ float sm[];
    float* ws   = sm;                 // [96][260] weight staging (init only)
    float* hbuf = sm + 96 * 260;      // [8][264]  h(w) fp32
    float* gh   = hbuf + 8 * 264;     // [2][8][100] per-k-half partials

    // ---- init: stage weight slice, preload A fragments into registers ----
    const float* WhD = Wh + (size_t)d * 768 * 256;
    for (int e = tid; e < 96 * 256; e += 384) {
        int rr = e >> 8, c = e & 255;
        int third = rr / 32, kr = rr % 32;
        ws[rr * 260 + c] = WhD[(size_t)(third * 256 + k0 + kr) * 256 + c];
    }
    __syncthreads();

    uint32_t afr[16][4];
    {
        const int row0 = mu * 16 + g;
#pragma unroll
        for (int ks = 0; ks < 16; ++ks) {
            int kc = kh * 128 + ks * 8;
            afr[ks][0] = f2tf(ws[row0 * 260 + kc + t]);
            afr[ks][1] = f2tf(ws[(row0 + 8) * 260 + kc + t]);
            afr[ks][2] = f2tf(ws[row0 * 260 + kc + t + 4]);
            afr[ks][3] = f2tf(ws[(row0 + 8) * 260 + kc + t + 4]);
        }
    }

    // epilogue mapping + biases (tid < 256: sl = sentence, kk = h-col in tile)
    const int sl = tid >> 5;
    const int kk = tid & 31;
    float bhr = 0.f, bhz = 0.f, bhn = 0.f;
    if (tid < 256) {
        bhr = bh_g[d * 768 + k0 + kk];
        bhz = bh_g[d * 768 + 256 + k0 + kk];
        bhn = bh_g[d * 768 + 512 + k0 + kk];
    }

    // exchange-region base for this (d, sg) group
    uint2* grp = g_Hx + (size_t)(d * 8 + sg) * 4 * 2048;   // 4 slots x 2048 pairs

    // poll assignment: 1024 uint4 per slot; thread handles tid, tid+384, tid+768
    const int npoll = (tid < 256) ? 3 : 2;

    __syncthreads();

    for (int w = 0; w < 128; ++w) {
        // prefetch gi(w) — independent of exchange
        float gir = 0.f, giz = 0.f, gin = 0.f;
        if (tid < 256) {
            const float* gi = g_Gi + (((size_t)d * 128 + w) * 64 + (s0 + sl)) * 768;
            gir = gi[k0 + kk];
            giz = gi[256 + k0 + kk];
            gin = gi[512 + k0 + kk];
        }

        // ---- poll tagged h(w) from slot w&3 straight into hbuf ----
        {
            const uint4* src = (const uint4*)(grp + (size_t)(w & 3) * 2048);
            const uint32_t tagw = (uint32_t)w;
            bool done[3] = {false, false, tid >= 256};
            int remaining = npoll;
            while (remaining) {
#pragma unroll
                for (int j = 0; j < 3; ++j) {
                    if (!done[j]) {
                        int idx = tid + j * 384;
                        uint4 v = __ldcg(src + idx);
                        if (v.y == tagw && v.w == tagw) {
                            int sent = idx >> 7;
                            int cp = (idx & 127) << 1;
                            hbuf[sent * 264 + cp]     = __uint_as_float(v.x);
                            hbuf[sent * 264 + cp + 1] = __uint_as_float(v.z);
                            done[j] = true;
                            --remaining;
                        }
                    }
                }
                if (remaining) __nanosleep(16);
            }
        }
        __syncthreads();

        // ---- mma: c[16 rows x 8 sent] per warp over this warp's 128 K-half ----
        float c[4] = {0.f, 0.f, 0.f, 0.f};
#pragma unroll
        for (int ks = 0; ks < 16; ++ks) {
            int kc = kh * 128 + ks * 8;
            uint32_t bfr[2];
            bfr[0] = f2tf(hbuf[g * 264 + kc + t]);
            bfr[1] = f2tf(hbuf[g * 264 + kc + t + 4]);
            mma8(c, afr[ks], bfr);
        }
        {
            float* base = gh + kh * 800;
            int r0w = mu * 16 + g;
            base[(2 * t) * 100 + r0w]         = c[0];
            base[(2 * t + 1) * 100 + r0w]     = c[1];
            base[(2 * t) * 100 + r0w + 8]     = c[2];
            base[(2 * t + 1) * 100 + r0w + 8] = c[3];
        }
        __syncthreads();

        // ---- GRU cell + tagged publish ----
        if (tid < 256) {
            float sr = gh[sl * 100 + kk]       + gh[800 + sl * 100 + kk];
            float sz = gh[sl * 100 + 32 + kk]  + gh[800 + sl * 100 + 32 + kk];
            float sn = gh[sl * 100 + 64 + kk]  + gh[800 + sl * 100 + 64 + kk];
            float r = sigf(gir + sr + bhr);
            float z = sigf(giz + sz + bhz);
            float n = tanhf(gin + r * (sn + bhn));
            float hprev = hbuf[sl * 264 + k0 + kk];
            float hnew = (1.f - z) * n + z * hprev;

            // tagged 8B publish to slot (w+1)&3 — value+tag land atomically
            uint2* dst = grp + (size_t)((w + 1) & 3) * 2048 + sl * 256 + k0 + kk;
            asm volatile("st.global.cg.v2.u32 [%0], {%1,%2};"
                         :: "l"(dst), "r"(__float_as_uint(hnew)), "r"((uint32_t)(w + 1))
                         : "memory");

            // plain store for k3 (consumed after kernel completes)
            g_H[(((size_t)d * 129 + (w + 1)) * 64 + (s0 + sl)) * 256 + k0 + kk] = hnew;
        }
        __syncthreads();   // protect hbuf/gh from next step's poll overwrite
    }
}

// K4: sent_summ[s][j] = sum_w u_word[s][w][j]
__global__ void k4_reduce() {
    int s = blockIdx.x;
    int j = blockIdx.y * 128 + threadIdx.x;
    const float* p = g_Uw + (size_t)s * 128 * 512 + j;
    float a = 0.f;
    for (int w = 0; w < 128; ++w) a += p[w * 512];
    g_sent[s * 512 + j] = a;
}

// K5b: sentence GRU gate with zero hidden state
__global__ void k5b_gate(const float* __restrict__ sbh) {
    int idx = blockIdx.x * 256 + threadIdx.x;
    if (idx >= 2 * 64 * 512) return;
    int d = idx >> 15;
    int rem = idx & 32767;
    int s = rem >> 9;
    int j = rem & 511;
    const float* gi = g_sgi + ((size_t)d * 64 + s) * 1536;
    float gir = gi[j], giz = gi[512 + j], gin = gi[1024 + j];
    float hr = sbh[d * 1536 + j];
    float hz = sbh[d * 1536 + 512 + j];
    float hn = sbh[d * 1536 + 1024 + j];
    float r = sigf(gir + hr);
    float z = sigf(giz + hz);
    float n = tanhf(gin + r * hn);
    g_sentenc[s * 1024 + d * 512 + j] = (1.f - z) * n;
}

// K6: doc sum, logits, log_softmax
__global__ void k6_final(const float* __restrict__ doW, const float* __restrict__ dob,
                         float* __restrict__ out, int out_size) {
    __shared__ float doc[1024];
    __shared__ float lg[16];
    int tid = threadIdx.x;
    for (int j = tid; j < 1024; j += 256) {
        float a = 0.f;
        for (int s = 0; s < 64; ++s) a += g_usent[s * 1024 + j];
        doc[j] = a;
    }
    __syncthreads();
    int wid = tid >> 5, lane = tid & 31;
    for (int c = wid; c < 13; c += 8) {
        float p = 0.f;
        for (int k = lane; k < 1024; k += 32) p += doc[k] * doW[c * 1024 + k];
#pragma unroll
        for (int o = 16; o > 0; o >>= 1) p += __shfl_xor_sync(0xffffffffu, p, o);
        if (lane == 0) lg[c] = p + dob[c];
    }
    __syncthreads();
    if (tid == 0) {
        float m = lg[0];
        for (int c = 1; c < 13; ++c) m = fmaxf(m, lg[c]);
        float sum = 0.f;
        for (int c = 0; c < 13; ++c) sum += expf(lg[c] - m);
        float lse = m + logf(sum);
        for (int c = 0; c < 13; ++c) out[out_size - 13 + c] = lg[c] - lse;
    }
}

// ---------------------------------------------------------------------------
extern "C" void kernel_launch(void* const* d_in, const int* in_sizes, int n_in,
                              void* d_out, int out_size) {
    const int*   doc = (const int*)  d_in[0];
    const float* emb = (const float*)d_in[1];
    const float* wWi = (const float*)d_in[2];
    const float* wWh = (const float*)d_in[3];
    const float* wbi = (const float*)d_in[4];
    const float* wbh = (const float*)d_in[5];
    const float* sWi = (const float*)d_in[6];
    const float* sbi = (const float*)d_in[8];
    const float* sbh = (const float*)d_in[9];
    const float* waW = (const float*)d_in[10];
    const float* wab = (const float*)d_in[11];
    const float* saW = (const float*)d_in[13];
    const float* sab = (const float*)d_in[14];
    const float* doW = (const float*)d_in[16];
    const float* dob = (const float*)d_in[17];
    float* out = (float*)d_out;

    // smem: ws 96*260 + hbuf 8*264 + gh 1600 floats = 114,688 B
    const int SMEM_K2 = (96 * 260 + 8 * 264 + 1600) * 4;
    cudaFuncSetAttribute(k2_rec, cudaFuncAttributeMaxDynamicSharedMemorySize, SMEM_K2);

    k0_init<<<64, 256>>>(out, out_size - 13);
    gemm_tf32<0><<<dim3(12, 64, 2), 256>>>(doc, emb, wWi, wbi);
    k2_rec<<<128, 384, SMEM_K2>>>(wWh, wbh);
    gemm_tf32<1><<<dim3(8, 64, 1), 256>>>(nullptr, nullptr, waW, wab);
    k4_reduce<<<dim3(64, 4), 128>>>();
    gemm_tf32<2><<<dim3(24, 1, 2), 256>>>(nullptr, nullptr, sWi, sbi);
    k5b_gate<<<256, 256>>>(sbh);
    gemm_tf32<3><<<dim3(16, 1, 1), 256>>>(nullptr, nullptr, saW, sab);
    k6_final<<<1, 256>>>(doW, dob, out, out_size);
}

// round 12
// speedup vs baseline: 1.4815x; 1.1429x over previous
#include <cuda_runtime.h>
#include <math.h>
#include <stdint.h>

// S=64, W=128, D=256, HW=256, HS=512, C=13

// ---------------------------------------------------------------------------
// Scratch (static device globals — no allocation allowed)
// ---------------------------------------------------------------------------
__device__ __align__(16) float g_Gi[2u*128*64*768];   // [d][w][s][768]
__device__ __align__(16) float g_H[2u*129*64*256];    // [d][w][s][256] (k3 input)
__device__ __align__(16) float g_Uw[64u*128*512];     // [s][w][512]
__device__ __align__(16) float g_sent[64*512];
__device__ __align__(16) float g_sgi[2*64*1536];
__device__ __align__(16) float g_sentenc[64*1024];
__device__ __align__(16) float g_usent[64*1024];
// tagged h-exchange ring: [d][sg][slot(4)][sent(8)][col(256)] of {h_bits, tag}
__device__ __align__(16) uint2 g_Hx[2*8*4*8*256];

__device__ __forceinline__ float sigf(float x) { return 1.f / (1.f + expf(-x)); }

__device__ __forceinline__ uint32_t f2tf(float f) {
    uint32_t u;
    asm("cvt.rna.tf32.f32 %0, %1;" : "=r"(u) : "f"(f));
    return u;
}

__device__ __forceinline__ void mma8(float c[4], const uint32_t a[4], const uint32_t b[2]) {
    asm volatile(
        "mma.sync.aligned.m16n8k8.row.col.f32.tf32.tf32.f32 "
        "{%0,%1,%2,%3}, {%4,%5,%6,%7}, {%8,%9}, {%0,%1,%2,%3};"
        : "+f"(c[0]), "+f"(c[1]), "+f"(c[2]), "+f"(c[3])
        : "r"(a[0]), "r"(a[1]), "r"(a[2]), "r"(a[3]), "r"(b[0]), "r"(b[1]));
}

// ---------------------------------------------------------------------------
// K0: attention-weight ones + reset h-exchange ring tags (replay safety)
// (byte-identical to the R8 passing version)
// ---------------------------------------------------------------------------
__global__ void k0_init(float* __restrict__ out, int ones_n) {
    int i = blockIdx.x * blockDim.x + threadIdx.x;
    int stride = gridDim.x * blockDim.x;
    for (int j = i; j < ones_n; j += stride) out[j] = 1.0f;
    // g_Hx: slot 0 = state h(0): value 0, tag 0; slots 1..3: tag invalid
    for (int j = i; j < 2 * 8 * 4 * 8 * 256; j += stride) {
        int slot = (j >> 11) & 3;
        g_Hx[j] = make_uint2(0u, slot == 0 ? 0u : 0xFFFFFFFFu);
    }
}

// ---------------------------------------------------------------------------
// Unified tf32 tensor-core GEMM v2: C[M,N] = act(A[M,K] @ B[N,K]^T + bias)
// vs R8: (1) RZ staging — raw fp32 bits, tf32 mma truncates in HW (no cvt),
//        (2) double-buffered DYNAMIC SMEM: 1 sync per K-tile, next-tile
//            global loads issued under the mma phase.
// Dynamic smem layout: As[2][128][36] then Bs[2][64][36]  (55,296 B)
// ---------------------------------------------------------------------------
#define GEMM_SMEM_BYTES ((2 * 128 * 36 + 2 * 64 * 36) * 4)

template<int MODE>
__global__ void __launch_bounds__(256) gemm_tf32(const int* __restrict__ doc,
                                                 const float* __restrict__ Aext,
                                                 const float* __restrict__ Bw,
                                                 const float* __restrict__ bias) {
    constexpr int K    = (MODE == 0) ? 256 : (MODE == 3) ? 1024 : 512;
    constexpr bool TANH = (MODE == 1) || (MODE == 3);
    constexpr int MV   = (MODE >= 2) ? 64 : 128;   // valid rows

    extern __shared__ float dsm[];
    float* AsBase = dsm;                    // [2][128][36]
    float* BsBase = dsm + 2 * 128 * 36;     // [2][64][36]
    __shared__ int toks[128];

    const int tid = threadIdx.x;
    const int z   = blockIdx.z;
    const int j0  = blockIdx.x * 64;
    const int r0  = blockIdx.y * 128;

    const float* B = Bw;
    const float* bi = bias;
    float* out;
    int ldC;
    if constexpr (MODE == 0) {
        B  += (size_t)z * 768 * 256;
        bi += z * 768;
        out = g_Gi + (size_t)z * 8192 * 768;
        ldC = 768;
    } else if constexpr (MODE == 1) {
        out = g_Uw; ldC = 512;
    } else if constexpr (MODE == 2) {
        B  += (size_t)z * 1536 * 512;
        bi += z * 1536;
        out = g_sgi + (size_t)z * 64 * 1536;
        ldC = 1536;
    } else {
        out = g_usent; ldC = 1024;
    }

    if constexpr (MODE == 0) {
        if (tid < 128) {
            int s = tid & 63, wl = tid >> 6;
            toks[tid] = doc[s * 128 + (r0 >> 6) + wl];
        }
        __syncthreads();
    }

    const int lane = tid & 31, wid = tid >> 5;
    const int g = lane >> 2, t = lane & 3;
    const int mbase = (wid & 1) * 64;
    const int nbase = (wid >> 1) * 16;

    float4 ra[4], rb[2];

    auto ldA = [&](int kt) {
#pragma unroll
        for (int it = 0; it < 4; ++it) {
            int f = tid + it * 256;
            int row = f >> 3;
            int c4 = (f & 7) << 2;
            int kg = kt + c4;
            const float* src;
            if constexpr (MODE == 0) {
                src = Aext + (size_t)toks[row] * 256 + kg;
            } else if constexpr (MODE == 1) {
                int r = r0 + row;
                int s = r >> 7, w = r & 127;
                int dsel = kg >> 8, kl = kg & 255;
                src = g_H + (((size_t)dsel * 129 + (w + 1)) * 64 + s) * 256 + kl;
            } else if constexpr (MODE == 2) {
                int rr = row < 64 ? row : 63;
                src = g_sent + (size_t)rr * 512 + kg;
            } else {
                int rr = row < 64 ? row : 63;
                src = g_sentenc + (size_t)rr * 1024 + kg;
            }
            ra[it] = *(const float4*)src;
        }
    };
    auto ldB = [&](int kt) {
#pragma unroll
        for (int it = 0; it < 2; ++it) {
            int f = tid + it * 256;
            int row = f >> 3;
            int c4 = (f & 7) << 2;
            rb[it] = *(const float4*)(B + (size_t)(j0 + row) * K + kt + c4);
        }
    };

    float acc[4][2][4] = {};

    ldA(0); ldB(0);
    int p = 0;
    for (int kt = 0; kt < K; kt += 32) {
        float* As = AsBase + p * 128 * 36;
        float* Bs = BsBase + p * 64 * 36;
        // stage current tile (raw fp32 bits — tf32 mma truncates in HW)
#pragma unroll
        for (int it = 0; it < 4; ++it) {
            int f = tid + it * 256;
            int row = f >> 3;
            int c4 = (f & 7) << 2;
            *(float4*)(As + row * 36 + c4) = ra[it];
        }
#pragma unroll
        for (int it = 0; it < 2; ++it) {
            int f = tid + it * 256;
            int row = f >> 3;
            int c4 = (f & 7) << 2;
            *(float4*)(Bs + row * 36 + c4) = rb[it];
        }
        __syncthreads();

        // prefetch next tile's globals — overlapped with mma below
        if (kt + 32 < K) { ldA(kt + 32); ldB(kt + 32); }

#pragma unroll
        for (int kc = 0; kc < 32; kc += 8) {
            uint32_t a[4][4], b[2][2];
#pragma unroll
            for (int mt = 0; mt < 4; ++mt) {
                int rr = mbase + mt * 16 + g;
                a[mt][0] = __float_as_uint(As[rr * 36 + kc + t]);
                a[mt][1] = __float_as_uint(As[(rr + 8) * 36 + kc + t]);
                a[mt][2] = __float_as_uint(As[rr * 36 + kc + t + 4]);
                a[mt][3] = __float_as_uint(As[(rr + 8) * 36 + kc + t + 4]);
            }
#pragma unroll
            for (int nt = 0; nt < 2; ++nt) {
                int nn = nbase + nt * 8 + g;
                b[nt][0] = __float_as_uint(Bs[nn * 36 + kc + t]);
                b[nt][1] = __float_as_uint(Bs[nn * 36 + kc + t + 4]);
            }
#pragma unroll
            for (int mt = 0; mt < 4; ++mt)
#pragma unroll
                for (int nt = 0; nt < 2; ++nt)
                    mma8(acc[mt][nt], a[mt], b[nt]);
        }
        p ^= 1;
    }

#pragma unroll
    for (int mt = 0; mt < 4; ++mt) {
#pragma unroll
        for (int nt = 0; nt < 2; ++nt) {
            int col = j0 + nbase + nt * 8 + 2 * t;
            float b0 = bi[col], b1 = bi[col + 1];
            int row = mbase + mt * 16 + g;
#pragma unroll
            for (int half = 0; half < 2; ++half) {
                int r = row + half * 8;
                if (r < MV) {
                    float v0 = acc[mt][nt][half * 2 + 0] + b0;
                    float v1 = acc[mt][nt][half * 2 + 1] + b1;
                    if (TANH) { v0 = tanhf(v0); v1 = tanhf(v1); }
                    float2 st = make_float2(v0, v1);
                    *(float2*)(out + (size_t)(r0 + r) * ldC + col) = st;
                }
            }
        }
    }
}

// ---------------------------------------------------------------------------
// K2: word GRU recurrence — tensor cores + TAGGED-DATA L2 exchange.
// (byte-identical to the R8 passing version)
// ---------------------------------------------------------------------------
__global__ void __launch_bounds__(384, 1) k2_rec(const float* __restrict__ Wh,
                                                 const float* __restrict__ bh_g) {
    const int b  = blockIdx.x;
    const int d  = b >> 6;
    const int kt = (b >> 3) & 7;
    const int sg = b & 7;
    const int k0 = kt * 32;
    const int s0 = sg * 8;
    const int tid  = threadIdx.x;
    const int lane = tid & 31;
    const int wu   = tid >> 5;       // 0..11
    const int mu   = wu % 6;         // m-tile (rows mu*16 .. +15 of 96)
    const int kh   = wu / 6;         // k-half (0:[0,128) 1:[128,256))
    const int g    = lane >> 2;      // 0..7
    const int t    = lane & 3;       // 0..3

    extern __shared__ float sm[];
    float* ws   = sm;                 // [96][260] weight staging (init only)
    float* hbuf = sm + 96 * 260;      // [8][264]  h(w) fp32
    float* gh   = hbuf + 8 * 264;     // [2][8][100] per-k-half partials

    // ---- init: stage weight slice, preload A fragments into registers ----
    const float* WhD = Wh + (size_t)d * 768 * 256;
    for (int e = tid; e < 96 * 256; e += 384) {
        int rr = e >> 8, c = e & 255;
        int third = rr / 32, kr = rr % 32;
        ws[rr * 260 + c] = WhD[(size_t)(third * 256 + k0 + kr) * 256 + c];
    }
    __syncthreads();

    uint32_t afr[16][4];
    {
        const int row0 = mu * 16 + g;
#pragma unroll
        for (int ks = 0; ks < 16; ++ks) {
            int kc = kh * 128 + ks * 8;
            afr[ks][0] = f2tf(ws[row0 * 260 + kc + t]);
            afr[ks][1] = f2tf(ws[(row0 + 8) * 260 + kc + t]);
            afr[ks][2] = f2tf(ws[row0 * 260 + kc + t + 4]);
            afr[ks][3] = f2tf(ws[(row0 + 8) * 260 + kc + t + 4]);
        }
    }

    // epilogue mapping + biases (tid < 256: sl = sentence, kk = h-col in tile)
    const int sl = tid >> 5;
    const int kk = tid & 31;
    float bhr = 0.f, bhz = 0.f, bhn = 0.f;
    if (tid < 256) {
        bhr = bh_g[d * 768 + k0 + kk];
        bhz = bh_g[d * 768 + 256 + k0 + kk];
        bhn = bh_g[d * 768 + 512 + k0 + kk];
    }

    // exchange-region base for this (d, sg) group
    uint2* grp = g_Hx + (size_t)(d * 8 + sg) * 4 * 2048;   // 4 slots x 2048 pairs

    // poll assignment: 1024 uint4 per slot; thread handles tid, tid+384, tid+768
    const int npoll = (tid < 256) ? 3 : 2;

    __syncthreads();

    for (int w = 0; w < 128; ++w) {
        // prefetch gi(w) — independent of exchange
        float gir = 0.f, giz = 0.f, gin = 0.f;
        if (tid < 256) {
            const float* gi = g_Gi + (((size_t)d * 128 + w) * 64 + (s0 + sl)) * 768;
            gir = gi[k0 + kk];
            giz = gi[256 + k0 + kk];
            gin = gi[512 + k0 + kk];
        }

        // ---- poll tagged h(w) from slot w&3 straight into hbuf ----
        {
            const uint4* src = (const uint4*)(grp + (size_t)(w & 3) * 2048);
            const uint32_t tagw = (uint32_t)w;
            bool done[3] = {false, false, tid >= 256};
            int remaining = npoll;
            while (remaining) {
#pragma unroll
                for (int j = 0; j < 3; ++j) {
                    if (!done[j]) {
                        int idx = tid + j * 384;
                        uint4 v = __ldcg(src + idx);
                        if (v.y == tagw && v.w == tagw) {
                            int sent = idx >> 7;
                            int cp = (idx & 127) << 1;
                            hbuf[sent * 264 + cp]     = __uint_as_float(v.x);
                            hbuf[sent * 264 + cp + 1] = __uint_as_float(v.z);
                            done[j] = true;
                            --remaining;
                        }
                    }
                }
                if (remaining) __nanosleep(16);
            }
        }
        __syncthreads();

        // ---- mma: c[16 rows x 8 sent] per warp over this warp's 128 K-half ----
        float c[4] = {0.f, 0.f, 0.f, 0.f};
#pragma unroll
        for (int ks = 0; ks < 16; ++ks) {
            int kc = kh * 128 + ks * 8;
            uint32_t bfr[2];
            bfr[0] = f2tf(hbuf[g * 264 + kc + t]);
            bfr[1] = f2tf(hbuf[g * 264 + kc + t + 4]);
            mma8(c, afr[ks], bfr);
        }
        {
            float* base = gh + kh * 800;
            int r0w = mu * 16 + g;
            base[(2 * t) * 100 + r0w]         = c[0];
            base[(2 * t + 1) * 100 + r0w]     = c[1];
            base[(2 * t) * 100 + r0w + 8]     = c[2];
            base[(2 * t + 1) * 100 + r0w + 8] = c[3];
        }
        __syncthreads();

        // ---- GRU cell + tagged publish ----
        if (tid < 256) {
            float sr = gh[sl * 100 + kk]       + gh[800 + sl * 100 + kk];
            float sz = gh[sl * 100 + 32 + kk]  + gh[800 + sl * 100 + 32 + kk];
            float sn = gh[sl * 100 + 64 + kk]  + gh[800 + sl * 100 + 64 + kk];
            float r = sigf(gir + sr + bhr);
            float z = sigf(giz + sz + bhz);
            float n = tanhf(gin + r * (sn + bhn));
            float hprev = hbuf[sl * 264 + k0 + kk];
            float hnew = (1.f - z) * n + z * hprev;

            // tagged 8B publish to slot (w+1)&3 — value+tag land atomically
            uint2* dst = grp + (size_t)((w + 1) & 3) * 2048 + sl * 256 + k0 + kk;
            asm volatile("st.global.cg.v2.u32 [%0], {%1,%2};"
                         :: "l"(dst), "r"(__float_as_uint(hnew)), "r"((uint32_t)(w + 1))
                         : "memory");

            // plain store for k3 (consumed after kernel completes)
            g_H[(((size_t)d * 129 + (w + 1)) * 64 + (s0 + sl)) * 256 + k0 + kk] = hnew;
        }
        __syncthreads();   // protect hbuf/gh from next step's poll overwrite
    }
}

// K4: sent_summ[s][j] = sum_w u_word[s][w][j]
__global__ void k4_reduce() {
    int s = blockIdx.x;
    int j = blockIdx.y * 128 + threadIdx.x;
    const float* p = g_Uw + (size_t)s * 128 * 512 + j;
    float a = 0.f;
    for (int w = 0; w < 128; ++w) a += p[w * 512];
    g_sent[s * 512 + j] = a;
}

// K5b: sentence GRU gate with zero hidden state
__global__ void k5b_gate(const float* __restrict__ sbh) {
    int idx = blockIdx.x * 256 + threadIdx.x;
    if (idx >= 2 * 64 * 512) return;
    int d = idx >> 15;
    int rem = idx & 32767;
    int s = rem >> 9;
    int j = rem & 511;
    const float* gi = g_sgi + ((size_t)d * 64 + s) * 1536;
    float gir = gi[j], giz = gi[512 + j], gin = gi[1024 + j];
    float hr = sbh[d * 1536 + j];
    float hz = sbh[d * 1536 + 512 + j];
    float hn = sbh[d * 1536 + 1024 + j];
    float r = sigf(gir + hr);
    float z = sigf(giz + hz);
    float n = tanhf(gin + r * hn);
    g_sentenc[s * 1024 + d * 512 + j] = (1.f - z) * n;
}

// K6: doc sum, logits, log_softmax
__global__ void k6_final(const float* __restrict__ doW, const float* __restrict__ dob,
                         float* __restrict__ out, int out_size) {
    __shared__ float doc[1024];
    __shared__ float lg[16];
    int tid = threadIdx.x;
    for (int j = tid; j < 1024; j += 256) {
        float a = 0.f;
        for (int s = 0; s < 64; ++s) a += g_usent[s * 1024 + j];
        doc[j] = a;
    }
    __syncthreads();
    int wid = tid >> 5, lane = tid & 31;
    for (int c = wid; c < 13; c += 8) {
        float p = 0.f;
        for (int k = lane; k < 1024; k += 32) p += doc[k] * doW[c * 1024 + k];
#pragma unroll
        for (int o = 16; o > 0; o >>= 1) p += __shfl_xor_sync(0xffffffffu, p, o);
        if (lane == 0) lg[c] = p + dob[c];
    }
    __syncthreads();
    if (tid == 0) {
        float m = lg[0];
        for (int c = 1; c < 13; ++c) m = fmaxf(m, lg[c]);
        float sum = 0.f;
        for (int c = 0; c < 13; ++c) sum += expf(lg[c] - m);
        float lse = m + logf(sum);
        for (int c = 0; c < 13; ++c) out[out_size - 13 + c] = lg[c] - lse;
    }
}

// ---------------------------------------------------------------------------
extern "C" void kernel_launch(void* const* d_in, const int* in_sizes, int n_in,
                              void* d_out, int out_size) {
    const int*   doc = (const int*)  d_in[0];
    const float* emb = (const float*)d_in[1];
    const float* wWi = (const float*)d_in[2];
    const float* wWh = (const float*)d_in[3];
    const float* wbi = (const float*)d_in[4];
    const float* wbh = (const float*)d_in[5];
    const float* sWi = (const float*)d_in[6];
    const float* sbi = (const float*)d_in[8];
    const float* sbh = (const float*)d_in[9];
    const float* waW = (const float*)d_in[10];
    const float* wab = (const float*)d_in[11];
    const float* saW = (const float*)d_in[13];
    const float* sab = (const float*)d_in[14];
    const float* doW = (const float*)d_in[16];
    const float* dob = (const float*)d_in[17];
    float* out = (float*)d_out;

    // smem: ws 96*260 + hbuf 8*264 + gh 1600 floats = 114,688 B
    const int SMEM_K2 = (96 * 260 + 8 * 264 + 1600) * 4;
    cudaFuncSetAttribute(k2_rec, cudaFuncAttributeMaxDynamicSharedMemorySize, SMEM_K2);
    // gemm staging: 55,296 B dynamic
    cudaFuncSetAttribute(gemm_tf32<0>, cudaFuncAttributeMaxDynamicSharedMemorySize, GEMM_SMEM_BYTES);
    cudaFuncSetAttribute(gemm_tf32<1>, cudaFuncAttributeMaxDynamicSharedMemorySize, GEMM_SMEM_BYTES);
    cudaFuncSetAttribute(gemm_tf32<2>, cudaFuncAttributeMaxDynamicSharedMemorySize, GEMM_SMEM_BYTES);
    cudaFuncSetAttribute(gemm_tf32<3>, cudaFuncAttributeMaxDynamicSharedMemorySize, GEMM_SMEM_BYTES);

    k0_init<<<64, 256>>>(out, out_size - 13);
    gemm_tf32<0><<<dim3(12, 64, 2), 256, GEMM_SMEM_BYTES>>>(doc, emb, wWi, wbi);
    k2_rec<<<128, 384, SMEM_K2>>>(wWh, wbh);
    gemm_tf32<1><<<dim3(8, 64, 1), 256, GEMM_SMEM_BYTES>>>(nullptr, nullptr, waW, wab);
    k4_reduce<<<dim3(64, 4), 128>>>();
    gemm_tf32<2><<<dim3(24, 1, 2), 256, GEMM_SMEM_BYTES>>>(nullptr, nullptr, sWi, sbi);
    k5b_gate<<<256, 256>>>(sbh);
    gemm_tf32<3><<<dim3(16, 1, 1), 256, GEMM_SMEM_BYTES>>>(nullptr, nullptr, saW, sab);
    k6_final<<<1, 256>>>(doW, dob, out, out_size);
}